// round 12
// baseline (speedup 1.0000x reference)
#include <cuda_runtime.h>

// Problem constants (B=64, S=4096, D=256)
#define B_ 64
#define S_ 4096
#define D_ 256
#define NSPLIT 8
#define CHUNK (S_ / NSPLIT)            // 512 rows per block
#define NWARPS 8
#define THREADS 256
// Warp-private pipeline: warp owns 64 contiguous rows, 32 stages x 2 rows,
// TRIPLE buffered. Ring: 8 warps x 3 bufs x 2KB = 48KB. wait(2) keeps two
// 2KB stages per warp in flight while one is computed -> ~128KB/SM airborne.
#define STAGES 32
#define RING_F4 (NWARPS * 3 * 128)     // float4 units (48KB)

// Scratch: per (batch, split) partial accumulator + weight sum.
__device__ float g_acc[B_ * NSPLIT][D_];
__device__ float g_lsum[B_ * NSPLIT];
// Monotonic arrival counter per batch (mod NSPLIT detects last; replay-safe).
__device__ unsigned int g_cnt[B_];

// w = exp(tanh(x)) = e * exp(-2/(e^{2x}+1)); branch-free, robust at both tails.
__device__ __forceinline__ float exp_tanh(float x) {
    float t = __expf(2.0f * x);
    return 2.718281828f * __expf(__fdividef(-2.0f, t + 1.0f));
}

// 16-byte async copy, L2-only (streaming policy, bypasses L1).
__device__ __forceinline__ void cp16(float4* smem_dst, const float4* gsrc) {
    unsigned sa = (unsigned)__cvta_generic_to_shared(smem_dst);
    asm volatile("cp.async.cg.shared.global [%0], [%1], 16;\n" :: "r"(sa), "l"(gsrc));
}
#define CP_COMMIT()  asm volatile("cp.async.commit_group;\n" ::: "memory")
#define CP_WAIT(N)   asm volatile("cp.async.wait_group %0;\n" :: "n"(N) : "memory")

__global__ __launch_bounds__(THREADS) void att_fused(
    const float* __restrict__ aspect,   // [B, 1, D]
    const float* __restrict__ memory,   // [B, S, D]
    const float* __restrict__ W,        // [2D, 1]
    const float* __restrict__ bias,     // [1]
    float* __restrict__ out)            // [B, D]
{
    const int blk   = blockIdx.x;
    const int batch = blk / NSPLIT;
    const int split = blk % NSPLIT;
    const int tid   = threadIdx.x;
    const int warp  = tid >> 5;
    const int lane  = tid & 31;

    __shared__ float4 ring[RING_F4];    // 48KB
    __shared__ float s_red[NWARPS];
    __shared__ float s_abias;
    __shared__ float s_acc[D_];
    __shared__ float s_l[NWARPS];
    __shared__ unsigned int s_last;

    const float4* mem4 = (const float4*)memory
                       + (size_t)batch * (S_ * (D_ / 4))
                       + (size_t)split * CHUNK * (D_ / 4);
    // Warp w owns contiguous rows [64w, 64w+64) of the chunk.
    const float4* wbase = mem4 + (size_t)warp * 64 * (D_ / 4);

    // Self-consistent lane mapping: lane l copies AND reads float4 {l, 32+l}
    // of each row -> zero races, no barriers in the stream loop.
    float4* b0 = ring + warp * 384 + lane;   // stage layout: rows at +0,+32,+64,+96
    float4* b1 = b0 + 128;
    float4* b2 = b0 + 256;

    #define ISSUE(PB, SRC)                                          \
        { cp16((PB), (SRC));           cp16((PB) + 32, (SRC) + 32); \
          cp16((PB) + 64, (SRC) + 64); cp16((PB) + 96, (SRC) + 96); \
          CP_COMMIT(); }

    // ---- prologue: stages 0,1,2 -> b0,b1,b2 ----
    {
        const float4* s0 = wbase + lane;
        ISSUE(b0, s0)
        ISSUE(b1, s0 + 128)
        ISSUE(b2, s0 + 256)
    }

    // ---- aspect bias: dot(aspect[batch], Wa) + b (overlaps prologue flight) ----
    {
        float p = aspect[batch * D_ + tid] * W[D_ + tid];
        #pragma unroll
        for (int o = 16; o; o >>= 1) p += __shfl_xor_sync(0xffffffffu, p, o);
        if (lane == 0) s_red[warp] = p;
    }
    s_acc[tid] = 0.0f;
    __syncthreads();
    if (tid == 0) {
        float s = bias[0];
        #pragma unroll
        for (int w = 0; w < NWARPS; w++) s += s_red[w];
        s_abias = s;
    }
    __syncthreads();
    const float abias = s_abias;

    // ---- Wm in registers: lane l holds W4[l] and W4[32+l] ----
    const float4* W4 = (const float4*)W;
    const float4 wm0 = W4[lane];
    const float4 wm1 = W4[32 + lane];

    float4 a0 = make_float4(0.f, 0.f, 0.f, 0.f);
    float4 a1 = make_float4(0.f, 0.f, 0.f, 0.f);
    float lsum = 0.0f;

    // Per-stage body: 2 rows, ILP=2 shuffle chains.
    #define STAGE_BODY(PB)                                                      \
    {                                                                           \
        const float4 v0a = (PB)[0],  v1a = (PB)[32];                            \
        const float4 v0b = (PB)[64], v1b = (PB)[96];                            \
        float d0 = v0a.x*wm0.x + v0a.y*wm0.y + v0a.z*wm0.z + v0a.w*wm0.w        \
                 + v1a.x*wm1.x + v1a.y*wm1.y + v1a.z*wm1.z + v1a.w*wm1.w;       \
        float d1 = v0b.x*wm0.x + v0b.y*wm0.y + v0b.z*wm0.z + v0b.w*wm0.w        \
                 + v1b.x*wm1.x + v1b.y*wm1.y + v1b.z*wm1.z + v1b.w*wm1.w;       \
        _Pragma("unroll")                                                       \
        for (int o = 16; o; o >>= 1) {                                          \
            d0 += __shfl_xor_sync(0xffffffffu, d0, o);                          \
            d1 += __shfl_xor_sync(0xffffffffu, d1, o);                          \
        }                                                                       \
        const float w0 = exp_tanh(d0 + abias);                                  \
        const float w1 = exp_tanh(d1 + abias);                                  \
        lsum += w0 + w1;                                                        \
        a0.x += w0*v0a.x + w1*v0b.x;  a0.y += w0*v0a.y + w1*v0b.y;              \
        a0.z += w0*v0a.z + w1*v0b.z;  a0.w += w0*v0a.w + w1*v0b.w;              \
        a1.x += w0*v1a.x + w1*v1b.x;  a1.y += w0*v1a.y + w1*v1b.y;              \
        a1.z += w0*v1a.z + w1*v1b.z;  a1.w += w0*v1a.w + w1*v1b.w;              \
    }

    // ---- steady state: i = 0..26 (27 = multiple of 3 -> buf ptr constant) ----
    // wait(2): stage i arrived, two newer stages still flying.
    const float4* srcn = wbase + 384 + lane;   // stage i+3 source
    #pragma unroll 3
    for (int i = 0; i < 27; i++) {
        CP_WAIT(2);
        float4* pb = (i % 3 == 0) ? b0 : ((i % 3 == 1) ? b1 : b2);
        STAGE_BODY(pb)
        ISSUE(pb, srcn)                       // stage i+3 reuses stage i's buffer
        srcn += 128;
    }
    // ---- tail: compute 27,28 (issuing 30,31), then drain 29,30,31 ----
    CP_WAIT(2); STAGE_BODY(b0) ISSUE(b0, srcn) srcn += 128;   // stage 27, issue 30
    CP_WAIT(2); STAGE_BODY(b1) ISSUE(b1, srcn)                // stage 28, issue 31
    CP_WAIT(2); STAGE_BODY(b2)                                // stage 29
    CP_WAIT(1); STAGE_BODY(b0)                                // stage 30
    CP_WAIT(0); STAGE_BODY(b1)                                // stage 31
    #undef STAGE_BODY
    #undef ISSUE

    // ---- combine 8 warps via smem atomics (one shot) ----
    atomicAdd(&s_acc[lane * 4 + 0], a0.x);
    atomicAdd(&s_acc[lane * 4 + 1], a0.y);
    atomicAdd(&s_acc[lane * 4 + 2], a0.z);
    atomicAdd(&s_acc[lane * 4 + 3], a0.w);
    atomicAdd(&s_acc[128 + lane * 4 + 0], a1.x);
    atomicAdd(&s_acc[128 + lane * 4 + 1], a1.y);
    atomicAdd(&s_acc[128 + lane * 4 + 2], a1.z);
    atomicAdd(&s_acc[128 + lane * 4 + 3], a1.w);
    if (lane == 0) s_l[warp] = lsum;
    __syncthreads();

    // ---- publish this block's partial ----
    g_acc[blk][tid] = s_acc[tid];
    if (tid == 0) {
        float l = 0.f;
        #pragma unroll
        for (int w = 0; w < NWARPS; w++) l += s_l[w];
        g_lsum[blk] = l;
    }

    // ---- last block of this batch combines (threadfence-reduction pattern) ----
    __threadfence();
    if (tid == 0) {
        unsigned int old = atomicAdd(&g_cnt[batch], 1u);
        s_last = (((old + 1u) % NSPLIT) == 0u) ? 1u : 0u;
    }
    __syncthreads();

    if (s_last) {
        float acc = 0.f, l = 0.f;
        #pragma unroll
        for (int sp = 0; sp < NSPLIT; sp++) {
            acc += g_acc[batch * NSPLIT + sp][tid];
            l   += g_lsum[batch * NSPLIT + sp];
        }
        out[batch * D_ + tid] = acc / l;
    }
}

extern "C" void kernel_launch(void* const* d_in, const int* in_sizes, int n_in,
                              void* d_out, int out_size)
{
    const float* aspect = (const float*)d_in[0];   // [B,1,D]
    const float* memory = (const float*)d_in[1];   // [B,S,D]
    const float* W      = (const float*)d_in[2];   // [2D,1]
    const float* bias   = (const float*)d_in[3];   // [1]
    float* out = (float*)d_out;                    // [B,D]

    att_fused<<<B_ * NSPLIT, THREADS>>>(aspect, memory, W, bias, out);
}

// round 13
// speedup vs baseline: 1.1898x; 1.1898x over previous
#include <cuda_runtime.h>

// Problem constants (B=64, S=4096, D=256)
#define B_ 64
#define S_ 4096
#define D_ 256
#define NSPLIT 8
#define CHUNK (S_ / NSPLIT)             // 512 rows per block
#define NWARPS 8
#define THREADS 256
#define ROWS_PER_WARP (CHUNK / NWARPS)  // 64
#define RB 4                            // rows per warp-iteration (ILP batch)

// Scratch: per (batch, split) partial accumulator + weight sum.
__device__ float g_acc[B_ * NSPLIT][D_];
__device__ float g_lsum[B_ * NSPLIT];
// Monotonic arrival counter per batch (never reset; mod-NSPLIT detects last
// block of each call — graph-replay safe, deterministic output).
__device__ unsigned int g_cnt[B_];

// w = exp(tanh(x)) = e * exp(-2/(e^{2x}+1))
// Branch-free, robust: x -> -inf gives e^-1, x -> +inf gives e (t=inf -> div=0).
__device__ __forceinline__ float exp_tanh(float x) {
    float t = __expf(2.0f * x);
    return 2.718281828f * __expf(__fdividef(-2.0f, t + 1.0f));
}

__global__ __launch_bounds__(THREADS) void att_fused(
    const float* __restrict__ aspect,   // [B, 1, D]
    const float* __restrict__ memory,   // [B, S, D]
    const float* __restrict__ W,        // [2D, 1]
    const float* __restrict__ bias,     // [1]
    float* __restrict__ out)            // [B, D]
{
    const int blk   = blockIdx.x;
    const int batch = blk / NSPLIT;
    const int split = blk % NSPLIT;
    const int tid   = threadIdx.x;
    const int warp  = tid >> 5;
    const int lane  = tid & 31;

    __shared__ float s_red[NWARPS];
    __shared__ float s_abias;
    __shared__ float s_acc[D_];
    __shared__ float s_l[NWARPS];
    __shared__ unsigned int s_last;

    // ---- aspect bias: dot(aspect[batch], Wa) + b  (Wa = W[D:2D]) ----
    {
        float p = aspect[batch * D_ + tid] * W[D_ + tid];
        #pragma unroll
        for (int o = 16; o; o >>= 1) p += __shfl_xor_sync(0xffffffffu, p, o);
        if (lane == 0) s_red[warp] = p;
    }
    s_acc[tid] = 0.0f;
    __syncthreads();
    if (tid == 0) {
        float s = bias[0];
        #pragma unroll
        for (int w = 0; w < NWARPS; w++) s += s_red[w];
        s_abias = s;
    }
    __syncthreads();
    const float abias = s_abias;

    // ---- Wm in registers: lane l holds W4[l] and W4[32+l] ----
    const float4* W4 = (const float4*)W;
    const float4 wm0 = W4[lane];
    const float4 wm1 = W4[32 + lane];

    const float4* mem4 = (const float4*)memory
                       + (size_t)batch * (S_ * (D_ / 4))
                       + (size_t)split * CHUNK * (D_ / 4);

    float4 a0 = make_float4(0.f, 0.f, 0.f, 0.f);
    float4 a1 = make_float4(0.f, 0.f, 0.f, 0.f);
    float lsum = 0.0f;

    // RB independent rows per iteration: 2*RB front-batched LDG.128, RB
    // independent shuffle-reduction chains that pipeline.
    #pragma unroll 2
    for (int i = 0; i < ROWS_PER_WARP; i += RB) {
        float4 v0[RB], v1[RB];
        #pragma unroll
        for (int j = 0; j < RB; j++) {
            const float4* r = mem4 + (size_t)((i + j) * NWARPS + warp) * (D_ / 4);
            v0[j] = r[lane];
            v1[j] = r[32 + lane];
        }

        float dot[RB];
        #pragma unroll
        for (int j = 0; j < RB; j++)
            dot[j] = v0[j].x * wm0.x + v0[j].y * wm0.y + v0[j].z * wm0.z + v0[j].w * wm0.w
                   + v1[j].x * wm1.x + v1[j].y * wm1.y + v1[j].z * wm1.z + v1[j].w * wm1.w;

        #pragma unroll
        for (int o = 16; o; o >>= 1) {
            #pragma unroll
            for (int j = 0; j < RB; j++)
                dot[j] += __shfl_xor_sync(0xffffffffu, dot[j], o);
        }

        #pragma unroll
        for (int j = 0; j < RB; j++) {
            const float w = exp_tanh(dot[j] + abias);
            lsum += w;
            a0.x += w * v0[j].x; a0.y += w * v0[j].y;
            a0.z += w * v0[j].z; a0.w += w * v0[j].w;
            a1.x += w * v1[j].x; a1.y += w * v1[j].y;
            a1.z += w * v1[j].z; a1.w += w * v1[j].w;
        }
    }

    // ---- combine 8 warps via smem atomics (one shot) ----
    atomicAdd(&s_acc[lane * 4 + 0], a0.x);
    atomicAdd(&s_acc[lane * 4 + 1], a0.y);
    atomicAdd(&s_acc[lane * 4 + 2], a0.z);
    atomicAdd(&s_acc[lane * 4 + 3], a0.w);
    atomicAdd(&s_acc[128 + lane * 4 + 0], a1.x);
    atomicAdd(&s_acc[128 + lane * 4 + 1], a1.y);
    atomicAdd(&s_acc[128 + lane * 4 + 2], a1.z);
    atomicAdd(&s_acc[128 + lane * 4 + 3], a1.w);
    if (lane == 0) s_l[warp] = lsum;
    __syncthreads();

    // ---- publish this block's partial ----
    g_acc[blk][tid] = s_acc[tid];
    if (tid == 0) {
        float l = 0.f;
        #pragma unroll
        for (int w = 0; w < NWARPS; w++) l += s_l[w];
        g_lsum[blk] = l;
    }

    // ---- last block of this batch combines (threadfence-reduction pattern) ----
    __threadfence();
    if (tid == 0) {
        unsigned int old = atomicAdd(&g_cnt[batch], 1u);
        s_last = (((old + 1u) % NSPLIT) == 0u) ? 1u : 0u;
    }
    __syncthreads();

    if (s_last) {
        float acc = 0.f, l = 0.f;
        #pragma unroll
        for (int sp = 0; sp < NSPLIT; sp++) {
            acc += g_acc[batch * NSPLIT + sp][tid];
            l   += g_lsum[batch * NSPLIT + sp];
        }
        out[batch * D_ + tid] = acc / l;
    }
}

extern "C" void kernel_launch(void* const* d_in, const int* in_sizes, int n_in,
                              void* d_out, int out_size)
{
    const float* aspect = (const float*)d_in[0];   // [B,1,D]
    const float* memory = (const float*)d_in[1];   // [B,S,D]
    const float* W      = (const float*)d_in[2];   // [2D,1]
    const float* bias   = (const float*)d_in[3];   // [1]
    float* out = (float*)d_out;                    // [B,D]

    att_fused<<<B_ * NSPLIT, THREADS>>>(aspect, memory, W, bias, out);
}